// round 1
// baseline (speedup 1.0000x reference)
#include <cuda_runtime.h>
#include <cstdint>
#include <cstddef>

// ---------------------------------------------------------------------------
// DocumentCrossAttentionMHA: B=8, S=256, K=8, D=512, H=8  (L = S*K = 2048)
// Pipeline:
//   q   = Qin @ Wq^T + bq            [B*L, D]
//   k   = sent @ Wk^T + bk           [B*S, D]
//   v   = sent @ Wv^T + bv           [B*S, D]
//   vt  = per-(b,h) transpose of v   [B,H,hd,S]
//   s   = 0.125 * q_h @ k_h^T        [B,H,L,S]
//   s   = softmax(mask(s))
//   ctx = s @ v_h                    [B,L,D]
//   ao  = ctx @ Wo^T + bo            [B*L, D]   (written over q scratch)
//   out = mean_L( LN(Qin + ao) )     [B, D]
// ---------------------------------------------------------------------------

#define BM 128
#define BN 64
#define BK 16

static const int Bb   = 8;
static const int Ss   = 256;
static const int Dd   = 512;
static const int Hh   = 8;
static const int Ll   = 2048;    // S*K
static const int HD   = 64;      // D/H

__device__ float g_q  [16384 * 512];        // 32 MB  (q, later attn_out)
__device__ float g_k  [ 2048 * 512];        //  4 MB
__device__ float g_v  [ 2048 * 512];        //  4 MB
__device__ float g_vt [64 * 64 * 256];      //  4 MB  [B*H][hd][S]
__device__ float g_s  [64 * 2048 * 256];    // 128 MB [B*H][L][S]
__device__ float g_ctx[16384 * 512];        // 32 MB
__device__ float g_part[8 * 32 * 512];      // 0.5 MB partial LN sums

// ---------------------------------------------------------------------------
// Generalized batched GEMM: C[m][n] = alpha * sum_k A[m][k]*B[n][k] + bias[n]
// Per-z offsets: z -> (bz = z/HH, hz = z%HH), base += bz*s?b + hz*s?h
// Requires M%128==0, N%64==0, Kd%16==0, all bases/lds 16B-aligned.
// ---------------------------------------------------------------------------
__global__ __launch_bounds__(256) void gemm_tn(
    const float* __restrict__ A, const float* __restrict__ B,
    const float* __restrict__ bias, float* __restrict__ C,
    int M, int N, int Kd, int lda, int ldb, int ldc,
    int HH, long sAb, long sAh, long sBb, long sBh, long sCb, long sCh,
    float alpha)
{
    __shared__ float As[BK][BM + 4];
    __shared__ float Bs[BK][BN + 4];

    int z  = blockIdx.z;
    int bz = z / HH, hz = z - bz * HH;
    A += (size_t)bz * sAb + (size_t)hz * sAh;
    B += (size_t)bz * sBb + (size_t)hz * sBh;
    C += (size_t)bz * sCb + (size_t)hz * sCh;

    int m0 = blockIdx.y * BM;
    int n0 = blockIdx.x * BN;
    int tid  = threadIdx.x;
    int tx   = tid & 15;          // N direction (16 * 4 = 64)
    int ty   = tid >> 4;          // M direction (16 * 8 = 128)
    int lrow = tid >> 2;          // 0..63
    int lvec = tid & 3;           // float4 slot within BK

    const float* Ap = A + (size_t)(m0 + lrow) * lda + lvec * 4;
    const float* Bp = B + (size_t)(n0 + lrow) * ldb + lvec * 4;

    float acc[8][4];
#pragma unroll
    for (int i = 0; i < 8; i++)
#pragma unroll
        for (int j = 0; j < 4; j++) acc[i][j] = 0.f;

    for (int k0 = 0; k0 < Kd; k0 += BK) {
        float4 a0 = *(const float4*)(Ap + k0);
        float4 a1 = *(const float4*)(Ap + (size_t)64 * lda + k0);
        float4 b0 = *(const float4*)(Bp + k0);

        As[lvec * 4 + 0][lrow] = a0.x;
        As[lvec * 4 + 1][lrow] = a0.y;
        As[lvec * 4 + 2][lrow] = a0.z;
        As[lvec * 4 + 3][lrow] = a0.w;
        As[lvec * 4 + 0][lrow + 64] = a1.x;
        As[lvec * 4 + 1][lrow + 64] = a1.y;
        As[lvec * 4 + 2][lrow + 64] = a1.z;
        As[lvec * 4 + 3][lrow + 64] = a1.w;
        Bs[lvec * 4 + 0][lrow] = b0.x;
        Bs[lvec * 4 + 1][lrow] = b0.y;
        Bs[lvec * 4 + 2][lrow] = b0.z;
        Bs[lvec * 4 + 3][lrow] = b0.w;
        __syncthreads();

#pragma unroll
        for (int kk = 0; kk < BK; kk++) {
            float af[8], bf[4];
#pragma unroll
            for (int i = 0; i < 8; i++) af[i] = As[kk][ty * 8 + i];
#pragma unroll
            for (int j = 0; j < 4; j++) bf[j] = Bs[kk][tx * 4 + j];
#pragma unroll
            for (int i = 0; i < 8; i++)
#pragma unroll
                for (int j = 0; j < 4; j++) acc[i][j] += af[i] * bf[j];
        }
        __syncthreads();
    }

    float bv[4];
#pragma unroll
    for (int j = 0; j < 4; j++) bv[j] = bias ? bias[n0 + tx * 4 + j] : 0.f;

#pragma unroll
    for (int i = 0; i < 8; i++) {
        float* Cr = C + (size_t)(m0 + ty * 8 + i) * ldc + n0 + tx * 4;
        float4 o;
        o.x = alpha * acc[i][0] + bv[0];
        o.y = alpha * acc[i][1] + bv[1];
        o.z = alpha * acc[i][2] + bv[2];
        o.w = alpha * acc[i][3] + bv[3];
        *(float4*)Cr = o;
    }
}

// ---------------------------------------------------------------------------
// Per-(b,h) transpose: vt[bh][d][j] = v[b][j][h*64+d]
// ---------------------------------------------------------------------------
__global__ void transpose_v(const float* __restrict__ v, float* __restrict__ vt)
{
    __shared__ float t[32][33];
    int bh = blockIdx.z, b = bh >> 3, h = bh & 7;
    int j0 = blockIdx.x * 32;   // over S (8 blocks)
    int d0 = blockIdx.y * 32;   // over hd (2 blocks)
    int tx = threadIdx.x, ty = threadIdx.y;

#pragma unroll
    for (int r = 0; r < 32; r += 8)
        t[ty + r][tx] = v[((size_t)b * Ss + j0 + ty + r) * Dd + h * HD + d0 + tx];
    __syncthreads();
#pragma unroll
    for (int r = 0; r < 32; r += 8)
        vt[((size_t)bh * HD + d0 + ty + r) * Ss + j0 + tx] = t[tx][ty + r];
}

// ---------------------------------------------------------------------------
// Masked softmax, one warp per row of [B*H*L, S=256]
// ---------------------------------------------------------------------------
__global__ __launch_bounds__(256) void softmax_mask(
    float* __restrict__ P, const int* __restrict__ num_sents)
{
    int warp = threadIdx.x >> 5, lane = threadIdx.x & 31;
    long row = (long)blockIdx.x * 8 + warp;           // 131072 rows
    int b = (int)(row >> 14);                         // row / (H*L)
    float* p = P + row * Ss;
    int ns = num_sents[b];

    float v[8];
    float mx = -3.0e38f;
#pragma unroll
    for (int t = 0; t < 8; t++) {
        int j = lane + t * 32;
        float x = p[j];
        v[t] = (j < ns) ? x : -3.0e38f;
        mx = fmaxf(mx, v[t]);
    }
#pragma unroll
    for (int o = 16; o; o >>= 1) mx = fmaxf(mx, __shfl_xor_sync(0xffffffffu, mx, o));

    float s = 0.f;
#pragma unroll
    for (int t = 0; t < 8; t++) { v[t] = __expf(v[t] - mx); s += v[t]; }
#pragma unroll
    for (int o = 16; o; o >>= 1) s += __shfl_xor_sync(0xffffffffu, s, o);

    float inv = 1.f / s;
#pragma unroll
    for (int t = 0; t < 8; t++) p[lane + t * 32] = v[t] * inv;
}

// ---------------------------------------------------------------------------
// Residual + LayerNorm + partial mean over 64 rows per block.
// grid (32 chunks, 8 batches), 512 threads (one per column).
// ---------------------------------------------------------------------------
__global__ __launch_bounds__(512) void epilogue_ln(
    const float* __restrict__ qin, const float* __restrict__ ao,
    const float* __restrict__ lnw, const float* __restrict__ lnb,
    float* __restrict__ part)
{
    __shared__ float r1[16], r2[16], stats[2];
    int b = blockIdx.y, chunk = blockIdx.x;
    int col = threadIdx.x, wid = col >> 5, lane = col & 31;
    float w = lnw[col], bb = lnb[col];
    float acc = 0.f;
    size_t base = ((size_t)b * Ll + chunk * 64) * Dd + col;

    for (int r = 0; r < 64; r++) {
        size_t idx = base + (size_t)r * Dd;
        float x = qin[idx] + ao[idx];
        float s = x, s2 = x * x;
#pragma unroll
        for (int o = 16; o; o >>= 1) {
            s  += __shfl_xor_sync(0xffffffffu, s, o);
            s2 += __shfl_xor_sync(0xffffffffu, s2, o);
        }
        if (lane == 0) { r1[wid] = s; r2[wid] = s2; }
        __syncthreads();
        if (col < 32) {
            float a  = (col < 16) ? r1[col] : 0.f;
            float a2 = (col < 16) ? r2[col] : 0.f;
#pragma unroll
            for (int o = 8; o; o >>= 1) {
                a  += __shfl_xor_sync(0xffffffffu, a, o);
                a2 += __shfl_xor_sync(0xffffffffu, a2, o);
            }
            if (col == 0) { stats[0] = a; stats[1] = a2; }
        }
        __syncthreads();
        float mu  = stats[0] * (1.f / 512.f);
        float var = stats[1] * (1.f / 512.f) - mu * mu;
        float xn  = (x - mu) * rsqrtf(var + 1e-5f);
        acc += xn * w + bb;
    }
    part[((size_t)b * 32 + chunk) * Dd + col] = acc;
}

__global__ void final_reduce(const float* __restrict__ part, float* __restrict__ out)
{
    int b = blockIdx.x, col = threadIdx.x;
    float s = 0.f;
#pragma unroll
    for (int c = 0; c < 32; c++) s += part[((size_t)b * 32 + c) * Dd + col];
    out[b * Dd + col] = s * (1.f / 2048.f);
}

// ---------------------------------------------------------------------------
extern "C" void kernel_launch(void* const* d_in, const int* in_sizes, int n_in,
                              void* d_out, int out_size)
{
    (void)in_sizes; (void)n_in; (void)out_size;
    const float* qin  = (const float*)d_in[0];   // top_word_vecs [B,S,K,D] = [B,L,D]
    const float* sent = (const float*)d_in[1];   // sent_vecs    [B,S,D]
    const int*   ns   = (const int*)  d_in[2];   // num_sents    [B]
    const float* Wq   = (const float*)d_in[3];
    const float* bq   = (const float*)d_in[4];
    const float* Wk   = (const float*)d_in[5];
    const float* bk   = (const float*)d_in[6];
    const float* Wv   = (const float*)d_in[7];
    const float* bvv  = (const float*)d_in[8];
    const float* Wo   = (const float*)d_in[9];
    const float* bo   = (const float*)d_in[10];
    const float* lnw  = (const float*)d_in[11];
    const float* lnb  = (const float*)d_in[12];
    float* out = (float*)d_out;

    float *q, *k, *v, *vt, *s, *ctx, *part;
    cudaGetSymbolAddress((void**)&q,    g_q);
    cudaGetSymbolAddress((void**)&k,    g_k);
    cudaGetSymbolAddress((void**)&v,    g_v);
    cudaGetSymbolAddress((void**)&vt,   g_vt);
    cudaGetSymbolAddress((void**)&s,    g_s);
    cudaGetSymbolAddress((void**)&ctx,  g_ctx);
    cudaGetSymbolAddress((void**)&part, g_part);

    dim3 blk(256);

    // Q projection: [16384,512] = Qin @ Wq^T + bq
    gemm_tn<<<dim3(512 / BN, 16384 / BM, 1), blk>>>(
        qin, Wq, bq, q, 16384, 512, 512, 512, 512, 512,
        1, 0, 0, 0, 0, 0, 0, 1.f);

    // K projection: [2048,512]
    gemm_tn<<<dim3(512 / BN, 2048 / BM, 1), blk>>>(
        sent, Wk, bk, k, 2048, 512, 512, 512, 512, 512,
        1, 0, 0, 0, 0, 0, 0, 1.f);

    // V projection: [2048,512]
    gemm_tn<<<dim3(512 / BN, 2048 / BM, 1), blk>>>(
        sent, Wv, bvv, v, 2048, 512, 512, 512, 512, 512,
        1, 0, 0, 0, 0, 0, 0, 1.f);

    transpose_v<<<dim3(8, 2, 64), dim3(32, 8)>>>(v, vt);

    // Scores: per (b,h): [2048,256] = 0.125 * q_h @ k_h^T
    gemm_tn<<<dim3(256 / BN, 2048 / BM, 64), blk>>>(
        q, k, nullptr, s, 2048, 256, 64, 512, 512, 256,
        8,
        (long)Ll * Dd, (long)HD,          // A: q
        (long)Ss * Dd, (long)HD,          // B: k
        (long)Hh * Ll * Ss, (long)Ll * Ss,// C: s
        0.125f);

    softmax_mask<<<131072 / 8, 256>>>(s, ns);

    // Context: per (b,h): [2048,64] = P @ V  (via Vt, A·B^T form)
    gemm_tn<<<dim3(64 / BN, 2048 / BM, 64), blk>>>(
        s, vt, nullptr, ctx, 2048, 64, 256, 256, 256, 512,
        8,
        (long)Hh * Ll * Ss, (long)Ll * Ss, // A: probs
        (long)Hh * HD * Ss, (long)HD * Ss, // B: vt
        (long)Ll * Dd, (long)HD,           // C: ctx
        1.f);

    // Output projection: attn_out = ctx @ Wo^T + bo  (reuse q scratch)
    gemm_tn<<<dim3(512 / BN, 16384 / BM, 1), blk>>>(
        ctx, Wo, bo, q, 16384, 512, 512, 512, 512, 512,
        1, 0, 0, 0, 0, 0, 0, 1.f);

    // Residual + LN + partial mean, then final reduce (also initializes d_out)
    epilogue_ln<<<dim3(32, 8), 512>>>(qin, q, lnw, lnb, part);
    final_reduce<<<8, 512>>>(part, out);
}